// round 15
// baseline (speedup 1.0000x reference)
#include <cuda_runtime.h>
#include <cuda_fp16.h>

// LightGCN 3-layer propagation on GB300 (sm_103a) — CSR gather, deferred output.
// Round 14: block-local degree sort. Each block owns 32 consecutive rows and
// rank-sorts them by degree (warp-shuffle, ~50 cyc) so the 4 rows sharing a
// warp have near-equal degree -> recovers the ~34% masked-iteration waste of
// the 8-lane/row geometry while keeping edge/store locality intact.
//   x16  = fp16(concat(ue, ie))              (streaming convert)
//   layer1: hA[r] = sum norm*x16[col]
//   layer2: hB[r] = sum norm*hA[col]
//   layer3: out[r] = 0.25*(x_fp32 + hA + hB + sum norm*hB[col])

#define NU 200000
#define NI 100000
#define NN 300000
#define DIM 64
#define NE 1200000
#define NBLK ((NN + 1023) / 1024)   // 293 scan blocks

struct Edge { int c; float nm; };

__device__ int   g_cnt[NN];
__device__ int   g_offs[NN];
__device__ int   g_cur[NN];
__device__ int   g_bsum[NBLK];
__device__ float g_dinv[NN];
__device__ Edge  g_edge[NE];
__device__ __half g_x16[(size_t)NN * DIM];  // 38.4 MB fp16 x-table
__device__ __half g_hA[(size_t)NN * DIM];   // 38.4 MB
__device__ __half g_hB[(size_t)NN * DIM];   // 38.4 MB

__global__ void k_zero_cnt() {
    int i = blockIdx.x * blockDim.x + threadIdx.x;
    if (i < NN) g_cnt[i] = 0;
}

__global__ void k_count(const int* __restrict__ row) {
    int e = blockIdx.x * blockDim.x + threadIdx.x;
    if (e < NE) atomicAdd(&g_cnt[row[e]], 1);
}

// Block-level exclusive scan of g_cnt; also computes dinv.
__global__ void k_scan1() {
    __shared__ int sh[1024];
    int i = blockIdx.x * 1024 + threadIdx.x;
    int v = (i < NN) ? g_cnt[i] : 0;
    if (i < NN) g_dinv[i] = (v > 0) ? rsqrtf((float)v) : 0.0f;
    sh[threadIdx.x] = v;
    __syncthreads();
    for (int off = 1; off < 1024; off <<= 1) {
        int t = (threadIdx.x >= off) ? sh[threadIdx.x - off] : 0;
        __syncthreads();
        sh[threadIdx.x] += t;
        __syncthreads();
    }
    if (i < NN) g_offs[i] = sh[threadIdx.x] - v;
    if (threadIdx.x == 1023) g_bsum[blockIdx.x] = sh[1023];
}

// Each block sums the partials below it for its base; finalize offs + cursors.
__global__ void k_scan2() {
    __shared__ int base_sh;
    int b = blockIdx.x;
    if (threadIdx.x < 32) {
        int s = 0;
        for (int j = threadIdx.x; j < b; j += 32) s += g_bsum[j];
        #pragma unroll
        for (int o = 16; o; o >>= 1) s += __shfl_down_sync(0xffffffffu, s, o);
        if (threadIdx.x == 0) base_sh = s;
    }
    __syncthreads();
    int i = b * 1024 + threadIdx.x;
    if (i < NN) {
        int o = g_offs[i] + base_sh;
        g_offs[i] = o;
        g_cur[i]  = o;
    }
}

__global__ void k_fill(const int* __restrict__ row, const int* __restrict__ col) {
    int e = blockIdx.x * blockDim.x + threadIdx.x;
    if (e < NE) {
        int r = row[e], c = col[e];
        int pos = atomicAdd(&g_cur[r], 1);
        Edge ed;
        ed.c  = c;
        ed.nm = __ldg(&g_dinv[r]) * __ldg(&g_dinv[c]);
        g_edge[pos] = ed;
    }
}

// Streaming convert: x16 = fp16(concat(ue, ie)). One float4 -> uint2 per thread.
__global__ void k_cvt(const float4* __restrict__ ue, const float4* __restrict__ ie) {
    int i = blockIdx.x * blockDim.x + threadIdx.x;
    const int NF4 = NN * (DIM / 4);
    if (i >= NF4) return;
    float4 v = (i < NU * (DIM / 4)) ? __ldg(&ue[i]) : __ldg(&ie[i - NU * (DIM / 4)]);
    half2 lo = __floats2half2_rn(v.x, v.y);
    half2 hi = __floats2half2_rn(v.z, v.w);
    uint2 u;
    u.x = *reinterpret_cast<unsigned int*>(&lo);
    u.y = *reinterpret_cast<unsigned int*>(&hi);
    reinterpret_cast<uint2*>(g_x16)[i] = u;
}

// ---------- gather core: 8 lanes per row, lane li owns cols [li*8, li*8+8) ----

struct Acc8 { float4 a, b; };

__device__ __forceinline__ void fetch_u4(const uint4* __restrict__ src,
                                         int c, int li, float4& fa, float4& fb)
{
    uint4 u = __ldg(&src[(size_t)c * 8 + li]);
    half2 h0 = *reinterpret_cast<half2*>(&u.x);
    half2 h1 = *reinterpret_cast<half2*>(&u.y);
    half2 h2 = *reinterpret_cast<half2*>(&u.z);
    half2 h3 = *reinterpret_cast<half2*>(&u.w);
    float2 f0 = __half22float2(h0);
    float2 f1 = __half22float2(h1);
    float2 f2 = __half22float2(h2);
    float2 f3 = __half22float2(h3);
    fa = make_float4(f0.x, f0.y, f1.x, f1.y);
    fb = make_float4(f2.x, f2.y, f3.x, f3.y);
}

__device__ __forceinline__ void fma8(Acc8& acc, float nm,
                                     const float4& va, const float4& vb)
{
    acc.a.x += nm * va.x; acc.a.y += nm * va.y; acc.a.z += nm * va.z; acc.a.w += nm * va.w;
    acc.b.x += nm * vb.x; acc.b.y += nm * vb.y; acc.b.z += nm * vb.z; acc.b.w += nm * vb.w;
}

__device__ __forceinline__ uint4 pack_h8(const Acc8& v) {
    half2 h0 = __floats2half2_rn(v.a.x, v.a.y);
    half2 h1 = __floats2half2_rn(v.a.z, v.a.w);
    half2 h2 = __floats2half2_rn(v.b.x, v.b.y);
    half2 h3 = __floats2half2_rn(v.b.z, v.b.w);
    uint4 u;
    u.x = *reinterpret_cast<unsigned int*>(&h0);
    u.y = *reinterpret_cast<unsigned int*>(&h1);
    u.z = *reinterpret_cast<unsigned int*>(&h2);
    u.w = *reinterpret_cast<unsigned int*>(&h3);
    return u;
}

// Block-local degree sort: block owns rows [blockIdx.x*32, +32). Warp 0
// rank-sorts them by degree; sperm[rank] = local row index.
__device__ __forceinline__ void local_degree_sort(int* sperm) {
    if (threadIdx.x < 32) {
        int i = threadIdx.x;
        int d = g_cnt[blockIdx.x * 32 + i];
        int rank = 0;
        #pragma unroll
        for (int j = 0; j < 32; j++) {
            int dj = __shfl_sync(0xffffffffu, d, j);
            rank += (dj < d) || (dj == d && j < i);
        }
        sperm[rank] = i;
    }
    __syncthreads();
}

// Gather over an fp16 table. 4-wide MLP pipeline (batched edge + v loads).
__device__ __forceinline__ Acc8 row_gather_h16(
    int r, int li, const uint4* __restrict__ src)
{
    int start = g_offs[r];
    int cnt   = g_cnt[r];
    const int2* __restrict__ ep = reinterpret_cast<const int2*>(g_edge) + start;

    Acc8 acc;
    acc.a = make_float4(0.f, 0.f, 0.f, 0.f);
    acc.b = make_float4(0.f, 0.f, 0.f, 0.f);
    int j = 0;
    for (; j + 3 < cnt; j += 4) {
        int2 e0 = __ldg(&ep[j + 0]);
        int2 e1 = __ldg(&ep[j + 1]);
        int2 e2 = __ldg(&ep[j + 2]);
        int2 e3 = __ldg(&ep[j + 3]);
        float4 va0, vb0, va1, vb1, va2, vb2, va3, vb3;
        fetch_u4(src, e0.x, li, va0, vb0);
        fetch_u4(src, e1.x, li, va1, vb1);
        fetch_u4(src, e2.x, li, va2, vb2);
        fetch_u4(src, e3.x, li, va3, vb3);
        fma8(acc, __int_as_float(e0.y), va0, vb0);
        fma8(acc, __int_as_float(e1.y), va1, vb1);
        fma8(acc, __int_as_float(e2.y), va2, vb2);
        fma8(acc, __int_as_float(e3.y), va3, vb3);
    }
    if (j + 1 < cnt) {
        int2 e0 = __ldg(&ep[j + 0]);
        int2 e1 = __ldg(&ep[j + 1]);
        float4 va0, vb0, va1, vb1;
        fetch_u4(src, e0.x, li, va0, vb0);
        fetch_u4(src, e1.x, li, va1, vb1);
        fma8(acc, __int_as_float(e0.y), va0, vb0);
        fma8(acc, __int_as_float(e1.y), va1, vb1);
        j += 2;
    }
    if (j < cnt) {
        int2 e0 = __ldg(&ep[j]);
        float4 va0, vb0;
        fetch_u4(src, e0.x, li, va0, vb0);
        fma8(acc, __int_as_float(e0.y), va0, vb0);
    }
    return acc;
}

// Layer 1: hA = A_norm @ x16
__global__ void __launch_bounds__(256) k_layer1() {
    __shared__ int sperm[32];
    local_degree_sort(sperm);
    int r  = blockIdx.x * 32 + sperm[threadIdx.x >> 3];
    int li = threadIdx.x & 7;
    Acc8 acc = row_gather_h16(r, li, reinterpret_cast<const uint4*>(g_x16));
    reinterpret_cast<uint4*>(g_hA)[(size_t)r * 8 + li] = pack_h8(acc);
}

// Layer 2: hB = A_norm @ hA
__global__ void __launch_bounds__(256) k_layer2() {
    __shared__ int sperm[32];
    local_degree_sort(sperm);
    int r  = blockIdx.x * 32 + sperm[threadIdx.x >> 3];
    int li = threadIdx.x & 7;
    Acc8 acc = row_gather_h16(r, li, reinterpret_cast<const uint4*>(g_hA));
    reinterpret_cast<uint4*>(g_hB)[(size_t)r * 8 + li] = pack_h8(acc);
}

// Layer 3: out = 0.25 * (x_fp32 + hA + hB + A_norm @ hB)
__global__ void __launch_bounds__(256) k_layer3(
    const float4* __restrict__ ue, const float4* __restrict__ ie,
    float4* __restrict__ out)
{
    __shared__ int sperm[32];
    local_degree_sort(sperm);
    int r  = blockIdx.x * 32 + sperm[threadIdx.x >> 3];
    int li = threadIdx.x & 7;

    Acc8 h3 = row_gather_h16(r, li, reinterpret_cast<const uint4*>(g_hB));

    // lane owns cols [li*8, li*8+8) = two float4 slots (2*li, 2*li+1)
    size_t oi = (size_t)r * 16 + li * 2;
    float4 xa, xb;
    if (r < NU) {
        xa = __ldg(&ue[oi]); xb = __ldg(&ue[oi + 1]);
    } else {
        size_t ii = (size_t)(r - NU) * 16 + li * 2;
        xa = __ldg(&ie[ii]); xb = __ldg(&ie[ii + 1]);
    }
    float4 h1a, h1b, h2a, h2b;
    fetch_u4(reinterpret_cast<const uint4*>(g_hA), r, li, h1a, h1b);
    fetch_u4(reinterpret_cast<const uint4*>(g_hB), r, li, h2a, h2b);

    float4 oa, ob;
    oa.x = 0.25f * (xa.x + h1a.x + h2a.x + h3.a.x);
    oa.y = 0.25f * (xa.y + h1a.y + h2a.y + h3.a.y);
    oa.z = 0.25f * (xa.z + h1a.z + h2a.z + h3.a.z);
    oa.w = 0.25f * (xa.w + h1a.w + h2a.w + h3.a.w);
    ob.x = 0.25f * (xb.x + h1b.x + h2b.x + h3.b.x);
    ob.y = 0.25f * (xb.y + h1b.y + h2b.y + h3.b.y);
    ob.z = 0.25f * (xb.z + h1b.z + h2b.z + h3.b.z);
    ob.w = 0.25f * (xb.w + h1b.w + h2b.w + h3.b.w);
    out[oi]     = oa;
    out[oi + 1] = ob;
}

extern "C" void kernel_launch(void* const* d_in, const int* in_sizes, int n_in,
                              void* d_out, int out_size) {
    const float* ue = (const float*)d_in[0];
    const float* ie = (const float*)d_in[1];
    const int*   ei = (const int*)d_in[2];
    const int* row = ei;
    const int* col = ei + NE;
    float4* out = (float4*)d_out;

    const int B = 256;
    const int gN  = (NN + B - 1) / B;
    const int gE  = (NE + B - 1) / B;
    const int gF4 = ((NN * (DIM / 4)) + B - 1) / B;
    const int gL  = NN / 32;                   // 9375 blocks, 32 rows each (exact)

    // CSR build + fp16 x-table convert
    k_zero_cnt<<<gN, B>>>();
    k_count<<<gE, B>>>(row);
    k_scan1<<<NBLK, 1024>>>();
    k_scan2<<<NBLK, 1024>>>();
    k_fill<<<gE, B>>>(row, col);
    k_cvt<<<gF4, B>>>((const float4*)ue, (const float4*)ie);

    // Layers
    k_layer1<<<gL, B>>>();
    k_layer2<<<gL, B>>>();
    k_layer3<<<gL, B>>>((const float4*)ue, (const float4*)ie, out);
}

// round 16
// speedup vs baseline: 1.1107x; 1.1107x over previous
#include <cuda_runtime.h>
#include <cuda_fp16.h>

// LightGCN 3-layer propagation on GB300 (sm_103a) — CSR gather, deferred output.
// Round 15: revert block-local degree sort (regression; divergence line closed).
// Layer kernels identical to Round 13 (best: 201.2us). Build phase trimmed:
//   - g_cnt zeroing via cudaMemsetAsync (no kernel launch)
//   - k_cvt fused into k_count (independent work, overlapped)
//   - k_scan1 uses warp-shuffle scan (2 syncs instead of 20)
//   x16  = fp16(concat(ue, ie))
//   layer1: hA[r] = sum norm*x16[col]
//   layer2: hB[r] = sum norm*hA[col]
//   layer3: out[r] = 0.25*(x_fp32 + hA + hB + sum norm*hB[col])

#define NU 200000
#define NI 100000
#define NN 300000
#define DIM 64
#define NE 1200000
#define NBLK ((NN + 1023) / 1024)   // 293 scan blocks

struct Edge { int c; float nm; };

__device__ int   g_cnt[NN];
__device__ int   g_offs[NN];
__device__ int   g_cur[NN];
__device__ int   g_bsum[NBLK];
__device__ float g_dinv[NN];
__device__ Edge  g_edge[NE];
__device__ __half g_x16[(size_t)NN * DIM];  // 38.4 MB fp16 x-table
__device__ __half g_hA[(size_t)NN * DIM];   // 38.4 MB
__device__ __half g_hB[(size_t)NN * DIM];   // 38.4 MB

// Fused: degree histogram (edges) + fp16 x-table convert (grid-stride).
__global__ void k_count_cvt(const int* __restrict__ row,
                            const float4* __restrict__ ue,
                            const float4* __restrict__ ie)
{
    int t  = blockIdx.x * blockDim.x + threadIdx.x;
    int nt = gridDim.x * blockDim.x;

    if (t < NE) atomicAdd(&g_cnt[row[t]], 1);

    const int NF4 = NN * (DIM / 4);
    for (int i = t; i < NF4; i += nt) {
        float4 v = (i < NU * (DIM / 4)) ? __ldg(&ue[i])
                                        : __ldg(&ie[i - NU * (DIM / 4)]);
        half2 lo = __floats2half2_rn(v.x, v.y);
        half2 hi = __floats2half2_rn(v.z, v.w);
        uint2 u;
        u.x = *reinterpret_cast<unsigned int*>(&lo);
        u.y = *reinterpret_cast<unsigned int*>(&hi);
        reinterpret_cast<uint2*>(g_x16)[i] = u;
    }
}

// Block-level exclusive scan of g_cnt (warp-shuffle based); also computes dinv.
__global__ void k_scan1() {
    __shared__ int wsum[32];
    int tid  = threadIdx.x;
    int lane = tid & 31;
    int wid  = tid >> 5;
    int i = blockIdx.x * 1024 + tid;

    int v = (i < NN) ? g_cnt[i] : 0;
    if (i < NN) g_dinv[i] = (v > 0) ? rsqrtf((float)v) : 0.0f;

    // warp inclusive scan
    int s = v;
    #pragma unroll
    for (int o = 1; o < 32; o <<= 1) {
        int t = __shfl_up_sync(0xffffffffu, s, o);
        if (lane >= o) s += t;
    }
    if (lane == 31) wsum[wid] = s;
    __syncthreads();
    if (wid == 0) {
        int w = wsum[lane];
        #pragma unroll
        for (int o = 1; o < 32; o <<= 1) {
            int t = __shfl_up_sync(0xffffffffu, w, o);
            if (lane >= o) w += t;
        }
        wsum[lane] = w;
    }
    __syncthreads();
    int base = (wid > 0) ? wsum[wid - 1] : 0;
    if (i < NN) g_offs[i] = base + s - v;   // exclusive
    if (tid == 1023) g_bsum[blockIdx.x] = base + s;
}

// Each block sums the partials below it for its base; finalize offs + cursors.
__global__ void k_scan2() {
    __shared__ int base_sh;
    int b = blockIdx.x;
    if (threadIdx.x < 32) {
        int s = 0;
        for (int j = threadIdx.x; j < b; j += 32) s += g_bsum[j];
        #pragma unroll
        for (int o = 16; o; o >>= 1) s += __shfl_down_sync(0xffffffffu, s, o);
        if (threadIdx.x == 0) base_sh = s;
    }
    __syncthreads();
    int i = b * 1024 + threadIdx.x;
    if (i < NN) {
        int o = g_offs[i] + base_sh;
        g_offs[i] = o;
        g_cur[i]  = o;
    }
}

__global__ void k_fill(const int* __restrict__ row, const int* __restrict__ col) {
    int e = blockIdx.x * blockDim.x + threadIdx.x;
    if (e < NE) {
        int r = row[e], c = col[e];
        int pos = atomicAdd(&g_cur[r], 1);
        Edge ed;
        ed.c  = c;
        ed.nm = __ldg(&g_dinv[r]) * __ldg(&g_dinv[c]);
        g_edge[pos] = ed;
    }
}

// ---------- gather core: 8 lanes per row, lane li owns cols [li*8, li*8+8) ----

struct Acc8 { float4 a, b; };

__device__ __forceinline__ void fetch_u4(const uint4* __restrict__ src,
                                         int c, int li, float4& fa, float4& fb)
{
    uint4 u = __ldg(&src[(size_t)c * 8 + li]);
    half2 h0 = *reinterpret_cast<half2*>(&u.x);
    half2 h1 = *reinterpret_cast<half2*>(&u.y);
    half2 h2 = *reinterpret_cast<half2*>(&u.z);
    half2 h3 = *reinterpret_cast<half2*>(&u.w);
    float2 f0 = __half22float2(h0);
    float2 f1 = __half22float2(h1);
    float2 f2 = __half22float2(h2);
    float2 f3 = __half22float2(h3);
    fa = make_float4(f0.x, f0.y, f1.x, f1.y);
    fb = make_float4(f2.x, f2.y, f3.x, f3.y);
}

__device__ __forceinline__ void fma8(Acc8& acc, float nm,
                                     const float4& va, const float4& vb)
{
    acc.a.x += nm * va.x; acc.a.y += nm * va.y; acc.a.z += nm * va.z; acc.a.w += nm * va.w;
    acc.b.x += nm * vb.x; acc.b.y += nm * vb.y; acc.b.z += nm * vb.z; acc.b.w += nm * vb.w;
}

__device__ __forceinline__ uint4 pack_h8(const Acc8& v) {
    half2 h0 = __floats2half2_rn(v.a.x, v.a.y);
    half2 h1 = __floats2half2_rn(v.a.z, v.a.w);
    half2 h2 = __floats2half2_rn(v.b.x, v.b.y);
    half2 h3 = __floats2half2_rn(v.b.z, v.b.w);
    uint4 u;
    u.x = *reinterpret_cast<unsigned int*>(&h0);
    u.y = *reinterpret_cast<unsigned int*>(&h1);
    u.z = *reinterpret_cast<unsigned int*>(&h2);
    u.w = *reinterpret_cast<unsigned int*>(&h3);
    return u;
}

// Gather over an fp16 table. 4-wide MLP pipeline (batched edge + v loads).
__device__ __forceinline__ Acc8 row_gather_h16(
    int r, int li, const uint4* __restrict__ src)
{
    int start = g_offs[r];
    int cnt   = g_cnt[r];
    const int2* __restrict__ ep = reinterpret_cast<const int2*>(g_edge) + start;

    Acc8 acc;
    acc.a = make_float4(0.f, 0.f, 0.f, 0.f);
    acc.b = make_float4(0.f, 0.f, 0.f, 0.f);
    int j = 0;
    for (; j + 3 < cnt; j += 4) {
        int2 e0 = __ldg(&ep[j + 0]);
        int2 e1 = __ldg(&ep[j + 1]);
        int2 e2 = __ldg(&ep[j + 2]);
        int2 e3 = __ldg(&ep[j + 3]);
        float4 va0, vb0, va1, vb1, va2, vb2, va3, vb3;
        fetch_u4(src, e0.x, li, va0, vb0);
        fetch_u4(src, e1.x, li, va1, vb1);
        fetch_u4(src, e2.x, li, va2, vb2);
        fetch_u4(src, e3.x, li, va3, vb3);
        fma8(acc, __int_as_float(e0.y), va0, vb0);
        fma8(acc, __int_as_float(e1.y), va1, vb1);
        fma8(acc, __int_as_float(e2.y), va2, vb2);
        fma8(acc, __int_as_float(e3.y), va3, vb3);
    }
    if (j + 1 < cnt) {
        int2 e0 = __ldg(&ep[j + 0]);
        int2 e1 = __ldg(&ep[j + 1]);
        float4 va0, vb0, va1, vb1;
        fetch_u4(src, e0.x, li, va0, vb0);
        fetch_u4(src, e1.x, li, va1, vb1);
        fma8(acc, __int_as_float(e0.y), va0, vb0);
        fma8(acc, __int_as_float(e1.y), va1, vb1);
        j += 2;
    }
    if (j < cnt) {
        int2 e0 = __ldg(&ep[j]);
        float4 va0, vb0;
        fetch_u4(src, e0.x, li, va0, vb0);
        fma8(acc, __int_as_float(e0.y), va0, vb0);
    }
    return acc;
}

// Layer 1: hA = A_norm @ x16
__global__ void __launch_bounds__(256) k_layer1() {
    int t = blockIdx.x * blockDim.x + threadIdx.x;
    int r = t >> 3;
    if (r >= NN) return;
    int li = t & 7;
    Acc8 acc = row_gather_h16(r, li, reinterpret_cast<const uint4*>(g_x16));
    reinterpret_cast<uint4*>(g_hA)[(size_t)r * 8 + li] = pack_h8(acc);
}

// Layer 2: hB = A_norm @ hA
__global__ void __launch_bounds__(256) k_layer2() {
    int t = blockIdx.x * blockDim.x + threadIdx.x;
    int r = t >> 3;
    if (r >= NN) return;
    int li = t & 7;
    Acc8 acc = row_gather_h16(r, li, reinterpret_cast<const uint4*>(g_hA));
    reinterpret_cast<uint4*>(g_hB)[(size_t)r * 8 + li] = pack_h8(acc);
}

// Layer 3: out = 0.25 * (x_fp32 + hA + hB + A_norm @ hB)
__global__ void __launch_bounds__(256) k_layer3(
    const float4* __restrict__ ue, const float4* __restrict__ ie,
    float4* __restrict__ out)
{
    int t = blockIdx.x * blockDim.x + threadIdx.x;
    int r = t >> 3;
    if (r >= NN) return;
    int li = t & 7;

    Acc8 h3 = row_gather_h16(r, li, reinterpret_cast<const uint4*>(g_hB));

    // lane owns cols [li*8, li*8+8) = two float4 slots (2*li, 2*li+1)
    size_t oi = (size_t)r * 16 + li * 2;
    float4 xa, xb;
    if (r < NU) {
        xa = __ldg(&ue[oi]); xb = __ldg(&ue[oi + 1]);
    } else {
        size_t ii = (size_t)(r - NU) * 16 + li * 2;
        xa = __ldg(&ie[ii]); xb = __ldg(&ie[ii + 1]);
    }
    float4 h1a, h1b, h2a, h2b;
    fetch_u4(reinterpret_cast<const uint4*>(g_hA), r, li, h1a, h1b);
    fetch_u4(reinterpret_cast<const uint4*>(g_hB), r, li, h2a, h2b);

    float4 oa, ob;
    oa.x = 0.25f * (xa.x + h1a.x + h2a.x + h3.a.x);
    oa.y = 0.25f * (xa.y + h1a.y + h2a.y + h3.a.y);
    oa.z = 0.25f * (xa.z + h1a.z + h2a.z + h3.a.z);
    oa.w = 0.25f * (xa.w + h1a.w + h2a.w + h3.a.w);
    ob.x = 0.25f * (xb.x + h1b.x + h2b.x + h3.b.x);
    ob.y = 0.25f * (xb.y + h1b.y + h2b.y + h3.b.y);
    ob.z = 0.25f * (xb.z + h1b.z + h2b.z + h3.b.z);
    ob.w = 0.25f * (xb.w + h1b.w + h2b.w + h3.b.w);
    out[oi]     = oa;
    out[oi + 1] = ob;
}

extern "C" void kernel_launch(void* const* d_in, const int* in_sizes, int n_in,
                              void* d_out, int out_size) {
    const float* ue = (const float*)d_in[0];
    const float* ie = (const float*)d_in[1];
    const int*   ei = (const int*)d_in[2];
    const int* row = ei;
    const int* col = ei + NE;
    float4* out = (float4*)d_out;

    const int B = 256;
    const int gE = (NE + B - 1) / B;
    const int gL = ((NN * 8) + B - 1) / B;    // 8 lanes per row

    // Zero degree counters without a kernel launch (async memset is capturable).
    void* cnt_ptr = nullptr;
    cudaGetSymbolAddress(&cnt_ptr, g_cnt);
    cudaMemsetAsync(cnt_ptr, 0, NN * sizeof(int));

    // CSR build + fp16 x-table convert (fused)
    k_count_cvt<<<gE, B>>>(row, (const float4*)ue, (const float4*)ie);
    k_scan1<<<NBLK, 1024>>>();
    k_scan2<<<NBLK, 1024>>>();
    k_fill<<<gE, B>>>(row, col);

    // Layers (identical to Round 13)
    k_layer1<<<gL, B>>>();
    k_layer2<<<gL, B>>>();
    k_layer3<<<gL, B>>>((const float4*)ue, (const float4*)ie, out);
}